// round 13
// baseline (speedup 1.0000x reference)
#include <cuda_runtime.h>
#include <cuda_bf16.h>
#include <math.h>
#include <stdint.h>

#define NEGC 1000000000000.0f

// B=8, S=512, D=768, HEADS=16, HD=64, N=2048 cols, M=4096 rows
__device__ __align__(128) __nv_bfloat16 g_hid[4096 * 768];   // bf16 hidden
__device__ __align__(128) __nv_bfloat16 g_Wt[2048 * 768];    // W^T [n][k] bf16
__device__ __align__(128) __nv_bfloat16 g_q[128 * 512 * 64]; // [bh][s][d]
__device__ __align__(128) __nv_bfloat16 g_k[128 * 512 * 64];
__device__ float g_sin[512 * 32];
__device__ float g_cos[512 * 32];

// ---------------------------------------------------------------------------
// helpers
// ---------------------------------------------------------------------------
__device__ __forceinline__ uint32_t smem_u32(const void* p) {
    return (uint32_t)__cvta_generic_to_shared(p);
}
__device__ __forceinline__ void cp16(uint32_t dst, const void* src) {
    asm volatile("cp.async.cg.shared.global [%0], [%1], 16;\n" :: "r"(dst), "l"(src));
}
__device__ __forceinline__ void cp_commit() { asm volatile("cp.async.commit_group;\n"); }
template <int N> __device__ __forceinline__ void cp_wait() {
    asm volatile("cp.async.wait_group %0;\n" :: "n"(N));
}
// SW128 swizzled byte offset for 128B rows; chunk = 16B unit 0..7
__device__ __forceinline__ uint32_t swz(int row, int chunk) {
    return (uint32_t)(row * 128 + ((chunk ^ (row & 7)) << 4));
}
__device__ __forceinline__ void ldm4(uint32_t addr, uint32_t& r0, uint32_t& r1,
                                     uint32_t& r2, uint32_t& r3) {
    asm volatile("ldmatrix.sync.aligned.m8n8.x4.shared.b16 {%0,%1,%2,%3}, [%4];\n"
                 : "=r"(r0), "=r"(r1), "=r"(r2), "=r"(r3) : "r"(addr));
}
__device__ __forceinline__ void mma_bf16(float* c, const uint32_t* a, const uint32_t* b) {
    asm volatile("mma.sync.aligned.m16n8k16.row.col.f32.bf16.bf16.f32 "
                 "{%0,%1,%2,%3},{%4,%5,%6,%7},{%8,%9},{%0,%1,%2,%3};\n"
                 : "+f"(c[0]), "+f"(c[1]), "+f"(c[2]), "+f"(c[3])
                 : "r"(a[0]), "r"(a[1]), "r"(a[2]), "r"(a[3]), "r"(b[0]), "r"(b[1]));
}

// ---------------------------------------------------------------------------
// prep kernel: block-range dispatch (rope table | hid->bf16 | W->W^T bf16)
// ---------------------------------------------------------------------------
__global__ __launch_bounds__(256) void prep_kernel(
    const float* __restrict__ hid, const float* __restrict__ W)
{
    const int bid = blockIdx.x;
    const int tid = threadIdx.x;

    if (bid < 64) {
        int idx = bid * 256 + tid;             // 16384
        int pos = idx >> 5, i = idx & 31;
        float inv = exp2f(-((float)(2 * i) / 64.0f) * 13.2877123795494f);
        float a = (float)pos * inv;
        float s, c;
        sincosf(a, &s, &c);
        g_sin[idx] = s;
        g_cos[idx] = c;
    } else if (bid < 64 + 3072) {
        int i = (bid - 64) * 256 + tid;        // 786432, 4 floats each
        float4 v = ((const float4*)hid)[i];
        __nv_bfloat162 lo, hi;
        lo.x = __float2bfloat16_rn(v.x); lo.y = __float2bfloat16_rn(v.y);
        hi.x = __float2bfloat16_rn(v.z); hi.y = __float2bfloat16_rn(v.w);
        ((__nv_bfloat162*)g_hid)[2 * i]     = lo;
        ((__nv_bfloat162*)g_hid)[2 * i + 1] = hi;
    } else {
        __shared__ float tile[32][33];
        int w = bid - 3136;                    // 0..1535
        int nt = (w & 63) * 32, kt = (w >> 6) * 32;
        int tx = tid & 31, ty = tid >> 5;      // 32 x 8
#pragma unroll
        for (int j = 0; j < 4; j++)
            tile[ty + j * 8][tx] = W[(size_t)(kt + ty + j * 8) * 2048 + nt + tx];
        __syncthreads();
#pragma unroll
        for (int j = 0; j < 4; j++) {
            int n = nt + ty + j * 8;
            g_Wt[(size_t)n * 768 + kt + tx] = __float2bfloat16_rn(tile[tx][ty + j * 8]);
        }
    }
}

// ---------------------------------------------------------------------------
// Projection GEMM (bf16 mma.sync) + bias + RoPE epilogue.
// Block 128x128, BK=64, 8 warps (2M x 4N), warp tile 64x32, 2-stage ring.
// Inner loop double-buffers ldmatrix fragments (R12 winner).
// ---------------------------------------------------------------------------
__global__ __launch_bounds__(256, 2) void proj_kernel(const float* __restrict__ bias) {
    extern __shared__ __align__(128) char smem[];
    __shared__ float sbias[128];
    const uint32_t sbase = smem_u32(smem);

    const int tid = threadIdx.x;
    const int lane = tid & 31;
    const int wid = tid >> 5;
    const int wm = (wid >> 2) * 64;    // 0,64
    const int wn = (wid & 3) * 32;     // 0,32,64,96
    const int m0 = blockIdx.y * 128;
    const int n0 = blockIdx.x * 128;
    const int h  = blockIdx.x;

    if (tid < 128) sbias[tid] = bias[n0 + tid];

    float acc[4][4][4];
#pragma unroll
    for (int i = 0; i < 4; i++)
#pragma unroll
        for (int j = 0; j < 4; j++)
#pragma unroll
            for (int r = 0; r < 4; r++) acc[i][j][r] = 0.0f;

    auto fill = [&](int stage, int kc) {
        const __nv_bfloat16* Ag = g_hid + (size_t)m0 * 768 + kc * 64;
        const __nv_bfloat16* Bg = g_Wt + (size_t)n0 * 768 + kc * 64;
        uint32_t sA = sbase + stage * 32768;
        uint32_t sB = sA + 16384;
#pragma unroll
        for (int i = 0; i < 4; i++) {
            int idx = i * 256 + tid;
            int row = idx >> 3, ch = idx & 7;
            cp16(sA + swz(row, ch), Ag + (size_t)row * 768 + ch * 8);
            cp16(sB + swz(row, ch), Bg + (size_t)row * 768 + ch * 8);
        }
    };

    auto load_frags = [&](uint32_t sA, uint32_t sB, int ks,
                          uint32_t a[4][4], uint32_t bfr[4][2]) {
#pragma unroll
        for (int mi = 0; mi < 4; mi++) {
            int row = wm + mi * 16 + (lane & 15);
            int ch = ks * 2 + (lane >> 4);
            ldm4(sA + swz(row, ch), a[mi][0], a[mi][1], a[mi][2], a[mi][3]);
        }
#pragma unroll
        for (int nb = 0; nb < 2; nb++) {
            int row = wn + nb * 16 + (lane & 7) + ((lane >> 4) << 3);
            int ch = ks * 2 + ((lane >> 3) & 1);
            uint32_t r0, r1, r2, r3;
            ldm4(sB + swz(row, ch), r0, r1, r2, r3);
            bfr[nb * 2][0] = r0;     bfr[nb * 2][1] = r1;
            bfr[nb * 2 + 1][0] = r2; bfr[nb * 2 + 1][1] = r3;
        }
    };

    fill(0, 0); cp_commit();

    for (int it = 0; it < 12; it++) {
        if (it + 1 < 12) {
            fill((it + 1) & 1, it + 1);
            cp_commit();
            cp_wait<1>();
        } else {
            cp_wait<0>();
        }
        __syncthreads();

        uint32_t sA = sbase + (it & 1) * 32768;
        uint32_t sB = sA + 16384;

        uint32_t aF[2][4][4];
        uint32_t bF[2][4][2];
        load_frags(sA, sB, 0, aF[0], bF[0]);
#pragma unroll
        for (int ks = 0; ks < 4; ks++) {
            int cur = ks & 1;
            if (ks < 3) load_frags(sA, sB, ks + 1, aF[cur ^ 1], bF[cur ^ 1]);
#pragma unroll
            for (int mi = 0; mi < 4; mi++)
#pragma unroll
                for (int nj = 0; nj < 4; nj++)
                    mma_bf16(acc[mi][nj], aF[cur][mi], bF[cur][nj]);
        }
        __syncthreads();
    }

    // Epilogue: bias + RoPE, write bf16 pairs to g_q / g_k in [bh][s][d]
    const int r0l = lane >> 2;
    const int c2l = (lane & 3) * 2;
#pragma unroll
    for (int nj = 0; nj < 4; nj++) {
        int ncol = wn + nj * 8 + c2l;        // 0..126 even, within head block
        int half = (ncol >> 6) & 1;          // 0=q, 1=k
        int d0 = ncol & 63;
        int pi = d0 >> 1;
        float b0v = sbias[ncol], b1v = sbias[ncol + 1];
        __nv_bfloat16* gb = half ? g_k : g_q;
#pragma unroll
        for (int mi = 0; mi < 4; mi++) {
#pragma unroll
            for (int rr = 0; rr < 2; rr++) {
                int m = m0 + wm + mi * 16 + r0l + rr * 8;
                int bi = m >> 9, s = m & 511;
                float x0 = acc[mi][nj][rr * 2 + 0] + b0v;
                float x1 = acc[mi][nj][rr * 2 + 1] + b1v;
                float sn = g_sin[s * 32 + pi];
                float cn = g_cos[s * 32 + pi];
                __nv_bfloat162 v;
                v.x = __float2bfloat16_rn(x0 * cn - x1 * sn);
                v.y = __float2bfloat16_rn(x1 * cn + x0 * sn);
                *(__nv_bfloat162*)(gb + ((size_t)((bi * 16 + h) * 512 + s)) * 64 + d0) = v;
            }
        }
    }
}

// ---------------------------------------------------------------------------
// logits: one block = one (bh, 128-row stripe). Q resident, K streamed
// through a 3-buffer cp.async ring. Below-diagonal tiles are pure stores
// done as flat float4 writes. Compute-tile epilogue pairs lanes via
// shfl.xor(1) to assemble 4 consecutive columns -> STG.128.
// Blocks with (bh & 15) == 0 also write tri_mask for their (b, stripe).
// dyn smem: [Q 16KB][K0 16KB][K1 16KB][K2 16KB]
// ---------------------------------------------------------------------------
__global__ __launch_bounds__(256) void logits_kernel(
    const int* __restrict__ tok, float* __restrict__ out,
    float* __restrict__ out_tri, int write_tri)
{
    extern __shared__ __align__(128) char lsm[];
    __shared__ float msk[512];

    const int tid = threadIdx.x;
    const int lane = tid & 31;
    const int wid = tid >> 5;
    const int wm = (wid >> 2) * 64;
    const int wn = (wid & 3) * 32;
    const int mt = blockIdx.x;          // 0..3
    const int bh = blockIdx.y;          // 0..127
    const int b = bh >> 4;
    const int m0 = mt << 7;

    const uint32_t sQ = smem_u32(lsm);
    const uint32_t sK0 = sQ + 16384;

    {
        const __nv_bfloat16* Qg = g_q + (size_t)(bh * 512 + m0) * 64;
        const __nv_bfloat16* Kg = g_k + (size_t)(bh * 512 + (mt << 7)) * 64;
#pragma unroll
        for (int i = 0; i < 4; i++) {
            int idx = i * 256 + tid;
            int row = idx >> 3, ch = idx & 7;
            cp16(sQ + swz(row, ch), Qg + (size_t)row * 64 + ch * 8);
            cp16(sK0 + swz(row, ch), Kg + (size_t)row * 64 + ch * 8);
        }
        cp_commit();
    }
    if (mt + 1 < 4) {
        const __nv_bfloat16* Kg = g_k + (size_t)(bh * 512 + ((mt + 1) << 7)) * 64;
        uint32_t sK = sK0 + 16384;
#pragma unroll
        for (int i = 0; i < 4; i++) {
            int idx = i * 256 + tid;
            int row = idx >> 3, ch = idx & 7;
            cp16(sK + swz(row, ch), Kg + (size_t)row * 64 + ch * 8);
        }
        cp_commit();
    }

    if (tid < 256) {
        msk[tid]       = (tok[b * 512 + tid] > 0) ? 1.0f : 0.0f;
        msk[tid + 256] = (tok[b * 512 + tid + 256] > 0) ? 1.0f : 0.0f;
    }
    __syncthreads();

    float* obase = out + ((size_t)bh << 18);
    const int r0l = lane >> 2;

    // pure-store region (all below-diagonal tiles): flat float4 writes,
    // cols [0, mt*128) of rows [m0, m0+128)
    if (mt > 0) {
        const int ncols4 = mt << 5;            // float4s per row
        const int total = 128 * ncols4;
        for (int i = tid; i < total; i += 256) {
            int mrow = i / ncols4;
            int n4 = (i - mrow * ncols4) * 4;
            int m = m0 + mrow;
            float mq = msk[m];
            float4 v;
            float* vv = (float*)&v;
#pragma unroll
            for (int jj = 0; jj < 4; jj++) {
                int n = n4 + jj;
                float t = 0.0f;
                if (mq == 0.0f)       t -= NEGC;
                if (msk[n] == 0.0f)   t -= NEGC;
                t -= NEGC;            // m > n guaranteed in this region
                vv[jj] = t;
            }
            *(float4*)(obase + (size_t)m * 512 + n4) = v;
        }
    }

    // compute tiles nt = mt..3
    for (int nt = mt; nt < 4; nt++) {
        int j = nt - mt;
        if (nt < 3) cp_wait<1>(); else cp_wait<0>();
        __syncthreads();
        if (nt + 2 < 4) {
            const __nv_bfloat16* Kg = g_k + (size_t)(bh * 512 + ((nt + 2) << 7)) * 64;
            uint32_t sK = sK0 + ((j + 2) % 3) * 16384;
#pragma unroll
            for (int i = 0; i < 4; i++) {
                int idx = i * 256 + tid;
                int row = idx >> 3, ch = idx & 7;
                cp16(sK + swz(row, ch), Kg + (size_t)row * 64 + ch * 8);
            }
            cp_commit();
        }

        uint32_t sK = sK0 + (j % 3) * 16384;
        float acc[4][4][4];
#pragma unroll
        for (int i = 0; i < 4; i++)
#pragma unroll
            for (int jj = 0; jj < 4; jj++)
#pragma unroll
                for (int r = 0; r < 4; r++) acc[i][jj][r] = 0.0f;

#pragma unroll
        for (int ks = 0; ks < 4; ks++) {
            uint32_t a[4][4];
#pragma unroll
            for (int mi = 0; mi < 4; mi++) {
                int row = wm + mi * 16 + (lane & 15);
                int ch = ks * 2 + (lane >> 4);
                ldm4(sQ + swz(row, ch), a[mi][0], a[mi][1], a[mi][2], a[mi][3]);
            }
            uint32_t bfr[4][2];
#pragma unroll
            for (int nb = 0; nb < 2; nb++) {
                int row = wn + nb * 16 + (lane & 7) + ((lane >> 4) << 3);
                int ch = ks * 2 + ((lane >> 3) & 1);
                uint32_t r0, r1, r2, r3;
                ldm4(sK + swz(row, ch), r0, r1, r2, r3);
                bfr[nb * 2][0] = r0;     bfr[nb * 2][1] = r1;
                bfr[nb * 2 + 1][0] = r2; bfr[nb * 2 + 1][1] = r3;
            }
#pragma unroll
            for (int mi = 0; mi < 4; mi++)
#pragma unroll
                for (int nj = 0; nj < 4; nj++)
                    mma_bf16(acc[mi][nj], a[mi], bfr[nj]);
        }

        // epilogue: lane-pair shuffle -> float4 stores
        // lane pair (L, L^1) holds cols (c,c+1) / (c+2,c+3) of same rows in
        // nj groups. Even lane assembles group 2jj, odd lane group 2jj+1.
        int n0 = nt << 7;
        const int sel = lane & 1;
        const int off4 = ((lane & 3) >> 1) * 4;    // 0 or 4 within 8-col group
#pragma unroll
        for (int mi = 0; mi < 4; mi++) {
#pragma unroll
            for (int rr = 0; rr < 2; rr++) {
                int m = m0 + wm + mi * 16 + r0l + rr * 8;
                float mq = msk[m];
#pragma unroll
                for (int jj = 0; jj < 2; jj++) {
                    float x0 = acc[mi][2 * jj][rr * 2 + 0];
                    float x1 = acc[mi][2 * jj][rr * 2 + 1];
                    float y0 = acc[mi][2 * jj + 1][rr * 2 + 0];
                    float y1 = acc[mi][2 * jj + 1][rr * 2 + 1];
                    // even lane sends its group-(2jj+1) pair, odd sends group-2jj
                    float s0 = __shfl_xor_sync(0xFFFFFFFFu, sel ? x0 : y0, 1);
                    float s1 = __shfl_xor_sync(0xFFFFFFFFu, sel ? x1 : y1, 1);
                    // assemble 4 consecutive cols of group (2jj + sel)
                    float q0, q1, q2, q3;
                    if (sel == 0) { q0 = x0; q1 = x1; q2 = s0; q3 = s1; }
                    else          { q0 = s0; q1 = s1; q2 = y0; q3 = y1; }
                    int n = n0 + wn + (2 * jj + sel) * 8 + off4;
                    float4 o;
                    float* ov = (float*)&o;
                    float qa[4] = {q0, q1, q2, q3};
#pragma unroll
                    for (int cc = 0; cc < 4; cc++) {
                        float v = qa[cc] * 0.125f;
                        int nn = n + cc;
                        if (mq == 0.0f)        v -= NEGC;
                        if (msk[nn] == 0.0f)   v -= NEGC;
                        if (m > nn)            v -= NEGC;
                        ov[cc] = v;
                    }
                    *(float4*)(obase + (size_t)m * 512 + n) = o;
                }
            }
        }
    }

    // tri_mask for this (b, stripe) — written by the h==0 block only
    if (write_tri && (bh & 15) == 0) {
        float* tbase = out_tri + ((size_t)b * 512 + m0) * 512;
        for (int i = tid; i < 16384; i += 256) {   // 16384 float4 = 128x512
            int mrow = i >> 7;                      // 0..127
            int n4 = (i & 127) * 4;                 // 0..508
            int m = m0 + mrow;
            float mq = msk[m];
            float4 v;
            float* vv = (float*)&v;
#pragma unroll
            for (int jj = 0; jj < 4; jj++) {
                int n = n4 + jj;
                vv[jj] = (m > n) ? 0.0f : mq * msk[n];
            }
            *(float4*)(tbase + (size_t)mrow * 512 + n4) = v;
        }
    }
}

// ---------------------------------------------------------------------------
extern "C" void kernel_launch(void* const* d_in, const int* in_sizes, int n_in,
                              void* d_out, int out_size) {
    const float* hidden = nullptr;
    const int*   tok    = nullptr;
    const float* Wm     = nullptr;
    const float* bias   = nullptr;
    for (int i = 0; i < n_in; i++) {
        switch (in_sizes[i]) {
            case 3145728: hidden = (const float*)d_in[i]; break;
            case 4096:    tok    = (const int*)d_in[i];   break;
            case 1572864: Wm     = (const float*)d_in[i]; break;
            case 2048:    bias   = (const float*)d_in[i]; break;
            default: break;
        }
    }

    float* out = (float*)d_out;
    const long long logits_elems = 33554432LL;
    int write_tri = (out_size >= 35651584) ? 1 : 0;
    float* out_tri = out + logits_elems;

    static int smem_set = 0;
    if (!smem_set) {
        cudaFuncSetAttribute(proj_kernel, cudaFuncAttributeMaxDynamicSharedMemorySize, 65536);
        cudaFuncSetAttribute(logits_kernel, cudaFuncAttributeMaxDynamicSharedMemorySize, 65536);
        smem_set = 1;
    }

    prep_kernel<<<4672, 256>>>(hidden, Wm);
    proj_kernel<<<dim3(16, 32), 256, 65536>>>(bias);
    logits_kernel<<<dim3(4, 128), 256, 65536>>>(tok, out, out_tri, write_tri);
}

// round 14
// speedup vs baseline: 1.0526x; 1.0526x over previous
#include <cuda_runtime.h>
#include <cuda_bf16.h>
#include <math.h>
#include <stdint.h>

#define NEGC 1000000000000.0f

// B=8, S=512, D=768, HEADS=16, HD=64, N=2048 cols, M=4096 rows
__device__ __align__(128) __nv_bfloat16 g_hid[4096 * 768];   // bf16 hidden
__device__ __align__(128) __nv_bfloat16 g_Wt[2048 * 768];    // W^T [n][k] bf16
__device__ __align__(128) __nv_bfloat16 g_q[128 * 512 * 64]; // [bh][s][d]
__device__ __align__(128) __nv_bfloat16 g_k[128 * 512 * 64];
__device__ float g_sin[512 * 32];
__device__ float g_cos[512 * 32];

// ---------------------------------------------------------------------------
// helpers
// ---------------------------------------------------------------------------
__device__ __forceinline__ uint32_t smem_u32(const void* p) {
    return (uint32_t)__cvta_generic_to_shared(p);
}
__device__ __forceinline__ void cp16(uint32_t dst, const void* src) {
    asm volatile("cp.async.cg.shared.global [%0], [%1], 16;\n" :: "r"(dst), "l"(src));
}
__device__ __forceinline__ void cp_commit() { asm volatile("cp.async.commit_group;\n"); }
template <int N> __device__ __forceinline__ void cp_wait() {
    asm volatile("cp.async.wait_group %0;\n" :: "n"(N));
}
// SW128 swizzled byte offset for 128B rows; chunk = 16B unit 0..7
__device__ __forceinline__ uint32_t swz(int row, int chunk) {
    return (uint32_t)(row * 128 + ((chunk ^ (row & 7)) << 4));
}
__device__ __forceinline__ void ldm4(uint32_t addr, uint32_t& r0, uint32_t& r1,
                                     uint32_t& r2, uint32_t& r3) {
    asm volatile("ldmatrix.sync.aligned.m8n8.x4.shared.b16 {%0,%1,%2,%3}, [%4];\n"
                 : "=r"(r0), "=r"(r1), "=r"(r2), "=r"(r3) : "r"(addr));
}
__device__ __forceinline__ void mma_bf16(float* c, const uint32_t* a, const uint32_t* b) {
    asm volatile("mma.sync.aligned.m16n8k16.row.col.f32.bf16.bf16.f32 "
                 "{%0,%1,%2,%3},{%4,%5,%6,%7},{%8,%9},{%0,%1,%2,%3};\n"
                 : "+f"(c[0]), "+f"(c[1]), "+f"(c[2]), "+f"(c[3])
                 : "r"(a[0]), "r"(a[1]), "r"(a[2]), "r"(a[3]), "r"(b[0]), "r"(b[1]));
}

// ---------------------------------------------------------------------------
// prep kernel: block-range dispatch (rope table | hid->bf16 | W->W^T bf16)
// ---------------------------------------------------------------------------
__global__ __launch_bounds__(256) void prep_kernel(
    const float* __restrict__ hid, const float* __restrict__ W)
{
    const int bid = blockIdx.x;
    const int tid = threadIdx.x;

    if (bid < 64) {
        int idx = bid * 256 + tid;             // 16384
        int pos = idx >> 5, i = idx & 31;
        float inv = exp2f(-((float)(2 * i) / 64.0f) * 13.2877123795494f);
        float a = (float)pos * inv;
        float s, c;
        sincosf(a, &s, &c);
        g_sin[idx] = s;
        g_cos[idx] = c;
    } else if (bid < 64 + 3072) {
        int i = (bid - 64) * 256 + tid;        // 786432, 4 floats each
        float4 v = ((const float4*)hid)[i];
        __nv_bfloat162 lo, hi;
        lo.x = __float2bfloat16_rn(v.x); lo.y = __float2bfloat16_rn(v.y);
        hi.x = __float2bfloat16_rn(v.z); hi.y = __float2bfloat16_rn(v.w);
        ((__nv_bfloat162*)g_hid)[2 * i]     = lo;
        ((__nv_bfloat162*)g_hid)[2 * i + 1] = hi;
    } else {
        __shared__ float tile[32][33];
        int w = bid - 3136;                    // 0..1535
        int nt = (w & 63) * 32, kt = (w >> 6) * 32;
        int tx = tid & 31, ty = tid >> 5;      // 32 x 8
#pragma unroll
        for (int j = 0; j < 4; j++)
            tile[ty + j * 8][tx] = W[(size_t)(kt + ty + j * 8) * 2048 + nt + tx];
        __syncthreads();
#pragma unroll
        for (int j = 0; j < 4; j++) {
            int n = nt + ty + j * 8;
            g_Wt[(size_t)n * 768 + kt + tx] = __float2bfloat16_rn(tile[tx][ty + j * 8]);
        }
    }
}

// ---------------------------------------------------------------------------
// Projection GEMM (bf16 mma.sync) + bias + RoPE epilogue.
// Block 128x128, BK=64, 8 warps (2M x 4N), warp tile 64x32, 2-stage ring.
// Inner loop double-buffers ldmatrix fragments (R12 winner).
// ---------------------------------------------------------------------------
__global__ __launch_bounds__(256, 2) void proj_kernel(const float* __restrict__ bias) {
    extern __shared__ __align__(128) char smem[];
    __shared__ float sbias[128];
    const uint32_t sbase = smem_u32(smem);

    const int tid = threadIdx.x;
    const int lane = tid & 31;
    const int wid = tid >> 5;
    const int wm = (wid >> 2) * 64;    // 0,64
    const int wn = (wid & 3) * 32;     // 0,32,64,96
    const int m0 = blockIdx.y * 128;
    const int n0 = blockIdx.x * 128;
    const int h  = blockIdx.x;

    if (tid < 128) sbias[tid] = bias[n0 + tid];

    float acc[4][4][4];
#pragma unroll
    for (int i = 0; i < 4; i++)
#pragma unroll
        for (int j = 0; j < 4; j++)
#pragma unroll
            for (int r = 0; r < 4; r++) acc[i][j][r] = 0.0f;

    auto fill = [&](int stage, int kc) {
        const __nv_bfloat16* Ag = g_hid + (size_t)m0 * 768 + kc * 64;
        const __nv_bfloat16* Bg = g_Wt + (size_t)n0 * 768 + kc * 64;
        uint32_t sA = sbase + stage * 32768;
        uint32_t sB = sA + 16384;
#pragma unroll
        for (int i = 0; i < 4; i++) {
            int idx = i * 256 + tid;
            int row = idx >> 3, ch = idx & 7;
            cp16(sA + swz(row, ch), Ag + (size_t)row * 768 + ch * 8);
            cp16(sB + swz(row, ch), Bg + (size_t)row * 768 + ch * 8);
        }
    };

    auto load_frags = [&](uint32_t sA, uint32_t sB, int ks,
                          uint32_t a[4][4], uint32_t bfr[4][2]) {
#pragma unroll
        for (int mi = 0; mi < 4; mi++) {
            int row = wm + mi * 16 + (lane & 15);
            int ch = ks * 2 + (lane >> 4);
            ldm4(sA + swz(row, ch), a[mi][0], a[mi][1], a[mi][2], a[mi][3]);
        }
#pragma unroll
        for (int nb = 0; nb < 2; nb++) {
            int row = wn + nb * 16 + (lane & 7) + ((lane >> 4) << 3);
            int ch = ks * 2 + ((lane >> 3) & 1);
            uint32_t r0, r1, r2, r3;
            ldm4(sB + swz(row, ch), r0, r1, r2, r3);
            bfr[nb * 2][0] = r0;     bfr[nb * 2][1] = r1;
            bfr[nb * 2 + 1][0] = r2; bfr[nb * 2 + 1][1] = r3;
        }
    };

    fill(0, 0); cp_commit();

    for (int it = 0; it < 12; it++) {
        if (it + 1 < 12) {
            fill((it + 1) & 1, it + 1);
            cp_commit();
            cp_wait<1>();
        } else {
            cp_wait<0>();
        }
        __syncthreads();

        uint32_t sA = sbase + (it & 1) * 32768;
        uint32_t sB = sA + 16384;

        uint32_t aF[2][4][4];
        uint32_t bF[2][4][2];
        load_frags(sA, sB, 0, aF[0], bF[0]);
#pragma unroll
        for (int ks = 0; ks < 4; ks++) {
            int cur = ks & 1;
            if (ks < 3) load_frags(sA, sB, ks + 1, aF[cur ^ 1], bF[cur ^ 1]);
#pragma unroll
            for (int mi = 0; mi < 4; mi++)
#pragma unroll
                for (int nj = 0; nj < 4; nj++)
                    mma_bf16(acc[mi][nj], aF[cur][mi], bF[cur][nj]);
        }
        __syncthreads();
    }

    // Epilogue: bias + RoPE, write bf16 pairs to g_q / g_k in [bh][s][d]
    const int r0l = lane >> 2;
    const int c2l = (lane & 3) * 2;
#pragma unroll
    for (int nj = 0; nj < 4; nj++) {
        int ncol = wn + nj * 8 + c2l;        // 0..126 even, within head block
        int half = (ncol >> 6) & 1;          // 0=q, 1=k
        int d0 = ncol & 63;
        int pi = d0 >> 1;
        float b0v = sbias[ncol], b1v = sbias[ncol + 1];
        __nv_bfloat16* gb = half ? g_k : g_q;
#pragma unroll
        for (int mi = 0; mi < 4; mi++) {
#pragma unroll
            for (int rr = 0; rr < 2; rr++) {
                int m = m0 + wm + mi * 16 + r0l + rr * 8;
                int bi = m >> 9, s = m & 511;
                float x0 = acc[mi][nj][rr * 2 + 0] + b0v;
                float x1 = acc[mi][nj][rr * 2 + 1] + b1v;
                float sn = g_sin[s * 32 + pi];
                float cn = g_cos[s * 32 + pi];
                __nv_bfloat162 v;
                v.x = __float2bfloat16_rn(x0 * cn - x1 * sn);
                v.y = __float2bfloat16_rn(x1 * cn + x0 * sn);
                *(__nv_bfloat162*)(gb + ((size_t)((bi * 16 + h) * 512 + s)) * 64 + d0) = v;
            }
        }
    }
}

// ---------------------------------------------------------------------------
// logits: one block = one (bh, 128-row stripe). Q resident, K streamed
// through a 3-buffer cp.async ring. Below-diagonal tiles are pure stores
// (bit-equivalent: fl(x-1e12) == -1e12 for |x| << half-ulp(1e12)).
// Blocks with (bh & 15) == 0 also write tri_mask for their (b, stripe).
// dyn smem: [Q 16KB][K0 16KB][K1 16KB][K2 16KB]
// ---------------------------------------------------------------------------
__global__ __launch_bounds__(256) void logits_kernel(
    const int* __restrict__ tok, float* __restrict__ out,
    float* __restrict__ out_tri, int write_tri)
{
    extern __shared__ __align__(128) char lsm[];
    __shared__ float msk[512];

    const int tid = threadIdx.x;
    const int lane = tid & 31;
    const int wid = tid >> 5;
    const int wm = (wid >> 2) * 64;
    const int wn = (wid & 3) * 32;
    const int mt = blockIdx.x;          // 0..3
    const int bh = blockIdx.y;          // 0..127
    const int b = bh >> 4;
    const int m0 = mt << 7;

    const uint32_t sQ = smem_u32(lsm);
    const uint32_t sK0 = sQ + 16384;

    {
        const __nv_bfloat16* Qg = g_q + (size_t)(bh * 512 + m0) * 64;
        const __nv_bfloat16* Kg = g_k + (size_t)(bh * 512 + (mt << 7)) * 64;
#pragma unroll
        for (int i = 0; i < 4; i++) {
            int idx = i * 256 + tid;
            int row = idx >> 3, ch = idx & 7;
            cp16(sQ + swz(row, ch), Qg + (size_t)row * 64 + ch * 8);
            cp16(sK0 + swz(row, ch), Kg + (size_t)row * 64 + ch * 8);
        }
        cp_commit();
    }
    if (mt + 1 < 4) {
        const __nv_bfloat16* Kg = g_k + (size_t)(bh * 512 + ((mt + 1) << 7)) * 64;
        uint32_t sK = sK0 + 16384;
#pragma unroll
        for (int i = 0; i < 4; i++) {
            int idx = i * 256 + tid;
            int row = idx >> 3, ch = idx & 7;
            cp16(sK + swz(row, ch), Kg + (size_t)row * 64 + ch * 8);
        }
        cp_commit();
    }

    if (tid < 256) {
        msk[tid]       = (tok[b * 512 + tid] > 0) ? 1.0f : 0.0f;
        msk[tid + 256] = (tok[b * 512 + tid + 256] > 0) ? 1.0f : 0.0f;
    }
    __syncthreads();

    float* obase = out + ((size_t)bh << 18);
    const int r0l = lane >> 2;
    const int c2l = (lane & 3) * 2;

    // pure-store tiles (below diagonal)
    for (int nt = 0; nt < mt; nt++) {
        int n0 = nt << 7;
#pragma unroll
        for (int mi = 0; mi < 4; mi++) {
#pragma unroll
            for (int rr = 0; rr < 2; rr++) {
                int m = m0 + wm + mi * 16 + r0l + rr * 8;
                float mq = msk[m];
#pragma unroll
                for (int nj = 0; nj < 4; nj++) {
                    int n = n0 + wn + nj * 8 + c2l;
                    float v0 = 0.0f, v1 = 0.0f;
                    if (mq == 0.0f)        { v0 -= NEGC; v1 -= NEGC; }
                    if (msk[n] == 0.0f)      v0 -= NEGC;
                    if (msk[n + 1] == 0.0f)  v1 -= NEGC;
                    v0 -= NEGC; v1 -= NEGC;   // m > n guaranteed
                    float2 o; o.x = v0; o.y = v1;
                    *(float2*)(obase + (size_t)m * 512 + n) = o;
                }
            }
        }
    }

    // compute tiles nt = mt..3
    for (int nt = mt; nt < 4; nt++) {
        int j = nt - mt;
        if (nt < 3) cp_wait<1>(); else cp_wait<0>();
        __syncthreads();
        if (nt + 2 < 4) {
            const __nv_bfloat16* Kg = g_k + (size_t)(bh * 512 + ((nt + 2) << 7)) * 64;
            uint32_t sK = sK0 + ((j + 2) % 3) * 16384;
#pragma unroll
            for (int i = 0; i < 4; i++) {
                int idx = i * 256 + tid;
                int row = idx >> 3, ch = idx & 7;
                cp16(sK + swz(row, ch), Kg + (size_t)row * 64 + ch * 8);
            }
            cp_commit();
        }

        uint32_t sK = sK0 + (j % 3) * 16384;
        float acc[4][4][4];
#pragma unroll
        for (int i = 0; i < 4; i++)
#pragma unroll
            for (int jj = 0; jj < 4; jj++)
#pragma unroll
                for (int r = 0; r < 4; r++) acc[i][jj][r] = 0.0f;

#pragma unroll
        for (int ks = 0; ks < 4; ks++) {
            uint32_t a[4][4];
#pragma unroll
            for (int mi = 0; mi < 4; mi++) {
                int row = wm + mi * 16 + (lane & 15);
                int ch = ks * 2 + (lane >> 4);
                ldm4(sQ + swz(row, ch), a[mi][0], a[mi][1], a[mi][2], a[mi][3]);
            }
            uint32_t bfr[4][2];
#pragma unroll
            for (int nb = 0; nb < 2; nb++) {
                int row = wn + nb * 16 + (lane & 7) + ((lane >> 4) << 3);
                int ch = ks * 2 + ((lane >> 3) & 1);
                uint32_t r0, r1, r2, r3;
                ldm4(sK + swz(row, ch), r0, r1, r2, r3);
                bfr[nb * 2][0] = r0;     bfr[nb * 2][1] = r1;
                bfr[nb * 2 + 1][0] = r2; bfr[nb * 2 + 1][1] = r3;
            }
#pragma unroll
            for (int mi = 0; mi < 4; mi++)
#pragma unroll
                for (int nj = 0; nj < 4; nj++)
                    mma_bf16(acc[mi][nj], a[mi], bfr[nj]);
        }

        int n0 = nt << 7;
#pragma unroll
        for (int mi = 0; mi < 4; mi++) {
#pragma unroll
            for (int rr = 0; rr < 2; rr++) {
                int m = m0 + wm + mi * 16 + r0l + rr * 8;
                float mq = msk[m];
#pragma unroll
                for (int nj = 0; nj < 4; nj++) {
                    int n = n0 + wn + nj * 8 + c2l;
                    float v0 = acc[mi][nj][rr * 2 + 0] * 0.125f;
                    float v1 = acc[mi][nj][rr * 2 + 1] * 0.125f;
                    if (mq == 0.0f)        { v0 -= NEGC; v1 -= NEGC; }
                    if (msk[n] == 0.0f)      v0 -= NEGC;
                    if (msk[n + 1] == 0.0f)  v1 -= NEGC;
                    if (m > n)               v0 -= NEGC;
                    if (m > n + 1)           v1 -= NEGC;
                    float2 o; o.x = v0; o.y = v1;
                    *(float2*)(obase + (size_t)m * 512 + n) = o;
                }
            }
        }
    }

    // tri_mask for this (b, stripe) — written by the h==0 block only
    if (write_tri && (bh & 15) == 0) {
        float* tbase = out_tri + ((size_t)b * 512 + m0) * 512;
        for (int i = tid; i < 16384; i += 256) {   // 16384 float4 = 128x512
            int mrow = i >> 7;                      // 0..127
            int n4 = (i & 127) * 4;                 // 0..508
            int m = m0 + mrow;
            float mq = msk[m];
            float4 v;
            float* vv = (float*)&v;
#pragma unroll
            for (int jj = 0; jj < 4; jj++) {
                int n = n4 + jj;
                vv[jj] = (m > n) ? 0.0f : mq * msk[n];
            }
            *(float4*)(tbase + (size_t)mrow * 512 + n4) = v;
        }
    }
}

// ---------------------------------------------------------------------------
extern "C" void kernel_launch(void* const* d_in, const int* in_sizes, int n_in,
                              void* d_out, int out_size) {
    const float* hidden = nullptr;
    const int*   tok    = nullptr;
    const float* Wm     = nullptr;
    const float* bias   = nullptr;
    for (int i = 0; i < n_in; i++) {
        switch (in_sizes[i]) {
            case 3145728: hidden = (const float*)d_in[i]; break;
            case 4096:    tok    = (const int*)d_in[i];   break;
            case 1572864: Wm     = (const float*)d_in[i]; break;
            case 2048:    bias   = (const float*)d_in[i]; break;
            default: break;
        }
    }

    float* out = (float*)d_out;
    const long long logits_elems = 33554432LL;
    int write_tri = (out_size >= 35651584) ? 1 : 0;
    float* out_tri = out + logits_elems;

    static int smem_set = 0;
    if (!smem_set) {
        cudaFuncSetAttribute(proj_kernel, cudaFuncAttributeMaxDynamicSharedMemorySize, 65536);
        cudaFuncSetAttribute(logits_kernel, cudaFuncAttributeMaxDynamicSharedMemorySize, 65536);
        smem_set = 1;
    }

    prep_kernel<<<4672, 256>>>(hidden, Wm);
    proj_kernel<<<dim3(16, 32), 256, 65536>>>(bias);
    logits_kernel<<<dim3(4, 128), 256, 65536>>>(tok, out, out_tri, write_tri);
}

// round 15
// speedup vs baseline: 1.1016x; 1.0466x over previous
#include <cuda_runtime.h>
#include <cuda_bf16.h>
#include <math.h>
#include <stdint.h>

#define NEGC 1000000000000.0f

// B=8, S=512, D=768, HEADS=16, HD=64, N=2048 cols, M=4096 rows
__device__ __align__(128) __nv_bfloat16 g_hid[4096 * 768];   // bf16 hidden
__device__ __align__(128) __nv_bfloat16 g_Wt[2048 * 768];    // W^T [n][k] bf16
__device__ __align__(128) __nv_bfloat16 g_q[128 * 512 * 64]; // [bh][s][d]
__device__ __align__(128) __nv_bfloat16 g_k[128 * 512 * 64];
__device__ float g_sin[512 * 32];
__device__ float g_cos[512 * 32];

// ---------------------------------------------------------------------------
// helpers
// ---------------------------------------------------------------------------
__device__ __forceinline__ uint32_t smem_u32(const void* p) {
    return (uint32_t)__cvta_generic_to_shared(p);
}
__device__ __forceinline__ void cp16(uint32_t dst, const void* src) {
    asm volatile("cp.async.cg.shared.global [%0], [%1], 16;\n" :: "r"(dst), "l"(src));
}
__device__ __forceinline__ void cp_commit() { asm volatile("cp.async.commit_group;\n"); }
template <int N> __device__ __forceinline__ void cp_wait() {
    asm volatile("cp.async.wait_group %0;\n" :: "n"(N));
}
// SW128 swizzled byte offset for 128B rows; chunk = 16B unit 0..7
__device__ __forceinline__ uint32_t swz(int row, int chunk) {
    return (uint32_t)(row * 128 + ((chunk ^ (row & 7)) << 4));
}
__device__ __forceinline__ void ldm4(uint32_t addr, uint32_t& r0, uint32_t& r1,
                                     uint32_t& r2, uint32_t& r3) {
    asm volatile("ldmatrix.sync.aligned.m8n8.x4.shared.b16 {%0,%1,%2,%3}, [%4];\n"
                 : "=r"(r0), "=r"(r1), "=r"(r2), "=r"(r3) : "r"(addr));
}
__device__ __forceinline__ void mma_bf16(float* c, const uint32_t* a, const uint32_t* b) {
    asm volatile("mma.sync.aligned.m16n8k16.row.col.f32.bf16.bf16.f32 "
                 "{%0,%1,%2,%3},{%4,%5,%6,%7},{%8,%9},{%0,%1,%2,%3};\n"
                 : "+f"(c[0]), "+f"(c[1]), "+f"(c[2]), "+f"(c[3])
                 : "r"(a[0]), "r"(a[1]), "r"(a[2]), "r"(a[3]), "r"(b[0]), "r"(b[1]));
}

// ---------------------------------------------------------------------------
// prep kernel: block-range dispatch (rope table | hid->bf16 | W->W^T bf16)
// ---------------------------------------------------------------------------
__global__ __launch_bounds__(256) void prep_kernel(
    const float* __restrict__ hid, const float* __restrict__ W)
{
    const int bid = blockIdx.x;
    const int tid = threadIdx.x;

    if (bid < 64) {
        int idx = bid * 256 + tid;             // 16384
        int pos = idx >> 5, i = idx & 31;
        float inv = exp2f(-((float)(2 * i) / 64.0f) * 13.2877123795494f);
        float a = (float)pos * inv;
        float s, c;
        sincosf(a, &s, &c);
        g_sin[idx] = s;
        g_cos[idx] = c;
    } else if (bid < 64 + 3072) {
        int i = (bid - 64) * 256 + tid;        // 786432, 4 floats each
        float4 v = ((const float4*)hid)[i];
        __nv_bfloat162 lo, hi;
        lo.x = __float2bfloat16_rn(v.x); lo.y = __float2bfloat16_rn(v.y);
        hi.x = __float2bfloat16_rn(v.z); hi.y = __float2bfloat16_rn(v.w);
        ((__nv_bfloat162*)g_hid)[2 * i]     = lo;
        ((__nv_bfloat162*)g_hid)[2 * i + 1] = hi;
    } else {
        __shared__ float tile[32][33];
        int w = bid - 3136;                    // 0..1535
        int nt = (w & 63) * 32, kt = (w >> 6) * 32;
        int tx = tid & 31, ty = tid >> 5;      // 32 x 8
#pragma unroll
        for (int j = 0; j < 4; j++)
            tile[ty + j * 8][tx] = W[(size_t)(kt + ty + j * 8) * 2048 + nt + tx];
        __syncthreads();
#pragma unroll
        for (int j = 0; j < 4; j++) {
            int n = nt + ty + j * 8;
            g_Wt[(size_t)n * 768 + kt + tx] = __float2bfloat16_rn(tile[tx][ty + j * 8]);
        }
    }
}

// ---------------------------------------------------------------------------
// Projection GEMM (bf16 mma.sync) + bias + RoPE epilogue.
// Block 128x128, BK=64, 8 warps (2M x 4N), warp tile 64x32, 2-stage ring.
// Inner loop double-buffers ldmatrix fragments (R12 winner).
// ---------------------------------------------------------------------------
__global__ __launch_bounds__(256, 2) void proj_kernel(const float* __restrict__ bias) {
    extern __shared__ __align__(128) char smem[];
    __shared__ float sbias[128];
    const uint32_t sbase = smem_u32(smem);

    const int tid = threadIdx.x;
    const int lane = tid & 31;
    const int wid = tid >> 5;
    const int wm = (wid >> 2) * 64;    // 0,64
    const int wn = (wid & 3) * 32;     // 0,32,64,96
    const int m0 = blockIdx.y * 128;
    const int n0 = blockIdx.x * 128;
    const int h  = blockIdx.x;

    if (tid < 128) sbias[tid] = bias[n0 + tid];

    float acc[4][4][4];
#pragma unroll
    for (int i = 0; i < 4; i++)
#pragma unroll
        for (int j = 0; j < 4; j++)
#pragma unroll
            for (int r = 0; r < 4; r++) acc[i][j][r] = 0.0f;

    auto fill = [&](int stage, int kc) {
        const __nv_bfloat16* Ag = g_hid + (size_t)m0 * 768 + kc * 64;
        const __nv_bfloat16* Bg = g_Wt + (size_t)n0 * 768 + kc * 64;
        uint32_t sA = sbase + stage * 32768;
        uint32_t sB = sA + 16384;
#pragma unroll
        for (int i = 0; i < 4; i++) {
            int idx = i * 256 + tid;
            int row = idx >> 3, ch = idx & 7;
            cp16(sA + swz(row, ch), Ag + (size_t)row * 768 + ch * 8);
            cp16(sB + swz(row, ch), Bg + (size_t)row * 768 + ch * 8);
        }
    };

    auto load_frags = [&](uint32_t sA, uint32_t sB, int ks,
                          uint32_t a[4][4], uint32_t bfr[4][2]) {
#pragma unroll
        for (int mi = 0; mi < 4; mi++) {
            int row = wm + mi * 16 + (lane & 15);
            int ch = ks * 2 + (lane >> 4);
            ldm4(sA + swz(row, ch), a[mi][0], a[mi][1], a[mi][2], a[mi][3]);
        }
#pragma unroll
        for (int nb = 0; nb < 2; nb++) {
            int row = wn + nb * 16 + (lane & 7) + ((lane >> 4) << 3);
            int ch = ks * 2 + ((lane >> 3) & 1);
            uint32_t r0, r1, r2, r3;
            ldm4(sB + swz(row, ch), r0, r1, r2, r3);
            bfr[nb * 2][0] = r0;     bfr[nb * 2][1] = r1;
            bfr[nb * 2 + 1][0] = r2; bfr[nb * 2 + 1][1] = r3;
        }
    };

    fill(0, 0); cp_commit();

    for (int it = 0; it < 12; it++) {
        if (it + 1 < 12) {
            fill((it + 1) & 1, it + 1);
            cp_commit();
            cp_wait<1>();
        } else {
            cp_wait<0>();
        }
        __syncthreads();

        uint32_t sA = sbase + (it & 1) * 32768;
        uint32_t sB = sA + 16384;

        uint32_t aF[2][4][4];
        uint32_t bF[2][4][2];
        load_frags(sA, sB, 0, aF[0], bF[0]);
#pragma unroll
        for (int ks = 0; ks < 4; ks++) {
            int cur = ks & 1;
            if (ks < 3) load_frags(sA, sB, ks + 1, aF[cur ^ 1], bF[cur ^ 1]);
#pragma unroll
            for (int mi = 0; mi < 4; mi++)
#pragma unroll
                for (int nj = 0; nj < 4; nj++)
                    mma_bf16(acc[mi][nj], aF[cur][mi], bF[cur][nj]);
        }
        __syncthreads();
    }

    // Epilogue: bias + RoPE, write bf16 pairs to g_q / g_k in [bh][s][d]
    const int r0l = lane >> 2;
    const int c2l = (lane & 3) * 2;
#pragma unroll
    for (int nj = 0; nj < 4; nj++) {
        int ncol = wn + nj * 8 + c2l;        // 0..126 even, within head block
        int half = (ncol >> 6) & 1;          // 0=q, 1=k
        int d0 = ncol & 63;
        int pi = d0 >> 1;
        float b0v = sbias[ncol], b1v = sbias[ncol + 1];
        __nv_bfloat16* gb = half ? g_k : g_q;
#pragma unroll
        for (int mi = 0; mi < 4; mi++) {
#pragma unroll
            for (int rr = 0; rr < 2; rr++) {
                int m = m0 + wm + mi * 16 + r0l + rr * 8;
                int bi = m >> 9, s = m & 511;
                float x0 = acc[mi][nj][rr * 2 + 0] + b0v;
                float x1 = acc[mi][nj][rr * 2 + 1] + b1v;
                float sn = g_sin[s * 32 + pi];
                float cn = g_cos[s * 32 + pi];
                __nv_bfloat162 v;
                v.x = __float2bfloat16_rn(x0 * cn - x1 * sn);
                v.y = __float2bfloat16_rn(x1 * cn + x0 * sn);
                *(__nv_bfloat162*)(gb + ((size_t)((bi * 16 + h) * 512 + s)) * 64 + d0) = v;
            }
        }
    }
}

// ---------------------------------------------------------------------------
// logits, tile-grained: one block = one 128x128 output tile of one (b,h).
// blockIdx.x = t in [0,16): t<10 -> compute tiles (mt<=nt enumerated),
// t>=10 -> below-diagonal pure-store tiles (flat float4 writes; exact:
// fl(x-1e12) == -1e12 for |x| << half-ulp(1e12)).
// tri_mask folded into t=10..13 blocks of bh%16==0 (one 128-row stripe each).
// dyn smem: [Q 16KB][K 16KB]
// ---------------------------------------------------------------------------
__global__ __launch_bounds__(256) void logits_kernel(
    const int* __restrict__ tok, float* __restrict__ out,
    float* __restrict__ out_tri, int write_tri)
{
    extern __shared__ __align__(128) char lsm[];
    __shared__ float msk[512];

    const int tid = threadIdx.x;
    const int t = blockIdx.x;           // 0..15
    const int bh = blockIdx.y;          // 0..127
    const int b = bh >> 4;

    // token masks for the whole sequence of this batch
    msk[tid]       = (tok[b * 512 + tid] > 0) ? 1.0f : 0.0f;
    msk[tid + 256] = (tok[b * 512 + tid + 256] > 0) ? 1.0f : 0.0f;

    float* obase = out + ((size_t)bh << 18);

    if (t < 10) {
        // ---- compute tile ----
        const signed char MT[10] = {0, 0, 0, 0, 1, 1, 1, 2, 2, 3};
        const signed char NT[10] = {0, 1, 2, 3, 1, 2, 3, 2, 3, 3};
        const int mt = MT[t], nt = NT[t];
        const int m0 = mt << 7, n0 = nt << 7;

        const int lane = tid & 31;
        const int wid = tid >> 5;
        const int wm = (wid >> 2) * 64;
        const int wn = (wid & 3) * 32;

        const uint32_t sQ = smem_u32(lsm);
        const uint32_t sK = sQ + 16384;

        const __nv_bfloat16* Qg = g_q + (size_t)(bh * 512 + m0) * 64;
        const __nv_bfloat16* Kg = g_k + (size_t)(bh * 512 + n0) * 64;
#pragma unroll
        for (int i = 0; i < 4; i++) {
            int idx = i * 256 + tid;
            int row = idx >> 3, ch = idx & 7;
            cp16(sQ + swz(row, ch), Qg + (size_t)row * 64 + ch * 8);
            cp16(sK + swz(row, ch), Kg + (size_t)row * 64 + ch * 8);
        }
        cp_commit();
        cp_wait<0>();
        __syncthreads();

        float acc[4][4][4];
#pragma unroll
        for (int i = 0; i < 4; i++)
#pragma unroll
            for (int jj = 0; jj < 4; jj++)
#pragma unroll
                for (int r = 0; r < 4; r++) acc[i][jj][r] = 0.0f;

#pragma unroll
        for (int ks = 0; ks < 4; ks++) {
            uint32_t a[4][4];
#pragma unroll
            for (int mi = 0; mi < 4; mi++) {
                int row = wm + mi * 16 + (lane & 15);
                int ch = ks * 2 + (lane >> 4);
                ldm4(sQ + swz(row, ch), a[mi][0], a[mi][1], a[mi][2], a[mi][3]);
            }
            uint32_t bfr[4][2];
#pragma unroll
            for (int nb = 0; nb < 2; nb++) {
                int row = wn + nb * 16 + (lane & 7) + ((lane >> 4) << 3);
                int ch = ks * 2 + ((lane >> 3) & 1);
                uint32_t r0, r1, r2, r3;
                ldm4(sK + swz(row, ch), r0, r1, r2, r3);
                bfr[nb * 2][0] = r0;     bfr[nb * 2][1] = r1;
                bfr[nb * 2 + 1][0] = r2; bfr[nb * 2 + 1][1] = r3;
            }
#pragma unroll
            for (int mi = 0; mi < 4; mi++)
#pragma unroll
                for (int nj = 0; nj < 4; nj++)
                    mma_bf16(acc[mi][nj], a[mi], bfr[nj]);
        }

        const int r0l = lane >> 2;
        const int c2l = (lane & 3) * 2;
#pragma unroll
        for (int mi = 0; mi < 4; mi++) {
#pragma unroll
            for (int rr = 0; rr < 2; rr++) {
                int m = m0 + wm + mi * 16 + r0l + rr * 8;
                float mq = msk[m];
#pragma unroll
                for (int nj = 0; nj < 4; nj++) {
                    int n = n0 + wn + nj * 8 + c2l;
                    float v0 = acc[mi][nj][rr * 2 + 0] * 0.125f;
                    float v1 = acc[mi][nj][rr * 2 + 1] * 0.125f;
                    if (mq == 0.0f)        { v0 -= NEGC; v1 -= NEGC; }
                    if (msk[n] == 0.0f)      v0 -= NEGC;
                    if (msk[n + 1] == 0.0f)  v1 -= NEGC;
                    if (m > n)               v0 -= NEGC;
                    if (m > n + 1)           v1 -= NEGC;
                    float2 o; o.x = v0; o.y = v1;
                    *(float2*)(obase + (size_t)m * 512 + n) = o;
                }
            }
        }
    } else {
        // ---- pure-store tile (below diagonal) ----
        const signed char MT2[6] = {1, 2, 2, 3, 3, 3};
        const signed char NT2[6] = {0, 0, 1, 0, 1, 2};
        const int mt = MT2[t - 10], nt = NT2[t - 10];
        const int m0 = mt << 7, n0 = nt << 7;

        __syncthreads();   // msk visible

        for (int i = tid; i < 4096; i += 256) {   // 4096 float4 = 128x128
            int mrow = i >> 5;
            int n4 = n0 + (i & 31) * 4;
            int m = m0 + mrow;
            float mq = msk[m];
            float4 v;
            float* vv = (float*)&v;
#pragma unroll
            for (int jj = 0; jj < 4; jj++) {
                int n = n4 + jj;
                float x = 0.0f;
                if (mq == 0.0f)      x -= NEGC;
                if (msk[n] == 0.0f)  x -= NEGC;
                x -= NEGC;           // m > n guaranteed in this region
                vv[jj] = x;
            }
            *(float4*)(obase + (size_t)m * 512 + n4) = v;
        }

        // tri_mask: blocks t=10..13 of head 0 each write one 128-row stripe
        if (write_tri && (bh & 15) == 0 && t < 14) {
            int stripe = t - 10;                   // 0..3
            int sm0 = stripe << 7;
            float* tbase = out_tri + ((size_t)b * 512 + sm0) * 512;
            for (int i = tid; i < 16384; i += 256) {   // 128x512 floats / 4
                int mrow = i >> 7;
                int n4 = (i & 127) * 4;
                int m = sm0 + mrow;
                float mq = msk[m];
                float4 v;
                float* vv = (float*)&v;
#pragma unroll
                for (int jj = 0; jj < 4; jj++) {
                    int n = n4 + jj;
                    vv[jj] = (m > n) ? 0.0f : mq * msk[n];
                }
                *(float4*)(tbase + (size_t)mrow * 512 + n4) = v;
            }
        }
    }
}

// ---------------------------------------------------------------------------
extern "C" void kernel_launch(void* const* d_in, const int* in_sizes, int n_in,
                              void* d_out, int out_size) {
    const float* hidden = nullptr;
    const int*   tok    = nullptr;
    const float* Wm     = nullptr;
    const float* bias   = nullptr;
    for (int i = 0; i < n_in; i++) {
        switch (in_sizes[i]) {
            case 3145728: hidden = (const float*)d_in[i]; break;
            case 4096:    tok    = (const int*)d_in[i];   break;
            case 1572864: Wm     = (const float*)d_in[i]; break;
            case 2048:    bias   = (const float*)d_in[i]; break;
            default: break;
        }
    }

    float* out = (float*)d_out;
    const long long logits_elems = 33554432LL;
    int write_tri = (out_size >= 35651584) ? 1 : 0;
    float* out_tri = out + logits_elems;

    static int smem_set = 0;
    if (!smem_set) {
        cudaFuncSetAttribute(proj_kernel, cudaFuncAttributeMaxDynamicSharedMemorySize, 65536);
        cudaFuncSetAttribute(logits_kernel, cudaFuncAttributeMaxDynamicSharedMemorySize, 32768);
        smem_set = 1;
    }

    prep_kernel<<<4672, 256>>>(hidden, Wm);
    proj_kernel<<<dim3(16, 32), 256, 65536>>>(bias);
    logits_kernel<<<dim3(16, 128), 256, 32768>>>(tok, out, out_tri, write_tri);
}